// round 8
// baseline (speedup 1.0000x reference)
#include <cuda_runtime.h>
#include <cstdint>

#define RR 5
#define NN 4096
#define DD 256
#define HH 64
#define BB 4096

// ---------------- scratch (static device globals; no allocs allowed) -------
__device__ float g_uw[RR*DD*HH];            // cumsum(u_weight)
__device__ float g_vw[RR*DD*HH];            // cumsum(v_weight)
__device__ float g_rowPart[RR*32*NN];
__device__ float g_colPart[RR*8*NN];
__device__ float g_cinv[RR*NN];             // index n
__device__ float g_rinv[RR*NN];             // index m
__device__ float g_Xh[(size_t)RR*HH*NN];    // X^T (tf32-rounded) [r][h][n]
__device__ float g_Y [(size_t)RR*NN*HH];    // Y   (tf32-rounded) [r][m][h]
__device__ float g_Tu[(size_t)RR*NN*HH];    // compact rows [r][pos][h]
__device__ float g_Tvt[(size_t)RR*HH*NN];   // [r][h][m]
__device__ int   g_uflag[NN];
__device__ int   g_ulist[NN];
__device__ int   g_upos[NN];
__device__ int   g_ucnt;

// ---------------- unique-u compaction --------------------------------------
__global__ void k_zero(){ g_uflag[blockIdx.x*256 + threadIdx.x] = 0; }
__global__ void k_flag(const int* __restrict__ u){
  g_uflag[u[blockIdx.x*256 + threadIdx.x]] = 1;   // same-value races: benign
}
__global__ void k_scan(){
  __shared__ int ss[1024];
  const int t = threadIdx.x;
  int f[4]; int s = 0;
  #pragma unroll
  for(int i=0;i<4;i++){ f[i] = g_uflag[t*4+i]; s += f[i]; }
  ss[t] = s; __syncthreads();
  for(int o=1; o<1024; o<<=1){
    int v = (t>=o) ? ss[t-o] : 0;
    __syncthreads();
    ss[t] += v;
    __syncthreads();
  }
  int base = ss[t] - s;   // exclusive prefix
  #pragma unroll
  for(int i=0;i<4;i++){
    if(f[i]){ const int n = t*4+i; g_ulist[base] = n; g_upos[n] = base; base++; }
  }
  if(t==1023) g_ucnt = ss[1023];
}

// ---------------- pass 1: row/col sums of support --------------------------
__global__ void k_sums(const float* __restrict__ supp){
  const int r = blockIdx.z, mc = blockIdx.x, nc = blockIdx.y;
  const int m0 = mc*128, n0 = nc*512;
  const int w = threadIdx.x>>5, lane = threadIdx.x&31;
  const float* base = supp + (size_t)r*NN*NN + m0 + lane*4;
  float cx=0.f, cy=0.f, cz=0.f, cw=0.f;
  float* rp = g_rowPart + ((size_t)r*32 + mc)*NN;
  #pragma unroll 4
  for(int i=0;i<128;i++){
    const int n = n0 + w*128 + i;
    const float4 v = *reinterpret_cast<const float4*>(base + (size_t)n*NN);
    float s = v.x+v.y+v.z+v.w;
    cx+=v.x; cy+=v.y; cz+=v.z; cw+=v.w;
    #pragma unroll
    for(int o=16;o;o>>=1) s += __shfl_xor_sync(0xffffffffu, s, o);
    if(lane==0) rp[n] = s;
  }
  __shared__ float sc[4][128];
  sc[w][lane*4+0]=cx; sc[w][lane*4+1]=cy; sc[w][lane*4+2]=cz; sc[w][lane*4+3]=cw;
  __syncthreads();
  if(threadIdx.x < 128){
    float s = sc[0][threadIdx.x]+sc[1][threadIdx.x]+sc[2][threadIdx.x]+sc[3][threadIdx.x];
    g_colPart[((size_t)r*8 + nc)*NN + m0 + threadIdx.x] = s;
  }
}

__global__ void k_reduce(){
  const int idx = blockIdx.x*256 + threadIdx.x;
  if(idx < RR*NN){
    const int r = idx/NN, n = idx%NN;
    float s=0.f;
    #pragma unroll
    for(int mc=0; mc<32; mc++) s += g_rowPart[((size_t)r*32+mc)*NN + n];
    g_cinv[idx] = (s>0.f)? rsqrtf(s) : 0.f;
  } else {
    const int j = idx - RR*NN;
    const int r = j/NN, m = j%NN;
    float s=0.f;
    #pragma unroll
    for(int nc=0; nc<8; nc++) s += g_colPart[((size_t)r*8+nc)*NN + m];
    g_rinv[j] = (s>0.f)? rsqrtf(s) : 0.f;
  }
}

__global__ void k_weights(const float* __restrict__ uw, const float* __restrict__ vw){
  const int i = blockIdx.x*256 + threadIdx.x;
  float au=0.f, av=0.f;
  #pragma unroll
  for(int r=0;r<RR;r++){
    au += uw[r*DD*HH + i]; g_uw[r*DD*HH + i] = au;
    av += vw[r*DD*HH + i]; g_vw[r*DD*HH + i] = av;
  }
}

// ---------------- TF32 / mma helpers ---------------------------------------
__device__ __forceinline__ unsigned f2tf(float x){
  unsigned r; asm("cvt.rna.tf32.f32 %0, %1;" : "=r"(r) : "f"(x)); return r;
}
__device__ __forceinline__ void mma8(float* c, const unsigned* a, const unsigned* b){
  asm volatile("mma.sync.aligned.m16n8k8.row.col.f32.tf32.tf32.f32 "
    "{%0,%1,%2,%3},{%4,%5,%6,%7},{%8,%9},{%0,%1,%2,%3};"
    : "+f"(c[0]),"+f"(c[1]),"+f"(c[2]),"+f"(c[3])
    : "r"(a[0]),"r"(a[1]),"r"(a[2]),"r"(a[3]),"r"(b[0]),"r"(b[1]));
}
__device__ __forceinline__ void cpa16(uint32_t dst, const void* src){
  asm volatile("cp.async.cg.shared.global [%0], [%1], 16;" :: "r"(dst), "l"(src));
}
#define CP_COMMIT asm volatile("cp.async.commit_group;" ::: "memory")
#define CP_WAIT1  asm volatile("cp.async.wait_group 1;"  ::: "memory")

// K-chunk 32 smem layout (word strides):
// A: rows x 32 words, stride 36 -> frag banks (4*l4+lc) distinct.
// B: 32 k-rows x 64/128 words, stride 72/136 (==8 mod 32) -> banks (8*lc+l4) distinct.
#define A_STR 36
#define BU_STR 72
#define BV_STR 136
#define STG_WORDS (128*A_STR + 32*BU_STR)   // 6912 words = 27648 B (z1 needs 6656)
#define STG_BYTES (STG_WORDS*4)
#define DYN_BYTES (3*STG_BYTES)             // 82944 B, occupancy 2

template<int BS>
__device__ __forceinline__ void load_frag(const unsigned* __restrict__ Ab,
                                          const unsigned* __restrict__ Bb,
                                          int wm,int wn,int l4,int lc,int k8,
                                          unsigned a[2][4], unsigned b[4][2]){
  #pragma unroll
  for(int mi=0; mi<2; mi++){
    const int rr = wm*32 + mi*16 + l4;
    a[mi][0]=Ab[rr*A_STR     + k8+lc];
    a[mi][1]=Ab[(rr+8)*A_STR + k8+lc];
    a[mi][2]=Ab[rr*A_STR     + k8+lc+4];
    a[mi][3]=Ab[(rr+8)*A_STR + k8+lc+4];
  }
  #pragma unroll
  for(int ni=0; ni<4; ni++){
    const int cc = wn*32 + ni*8 + l4;
    b[ni][0]=Bb[(k8+lc)*BS   + cc];
    b[ni][1]=Bb[(k8+lc+4)*BS + cc];
  }
}

template<int BS>
__device__ __forceinline__ void chunk_mma(const unsigned* __restrict__ Ab,
                                          const unsigned* __restrict__ Bb,
                                          int wm,int wn,int l4,int lc,
                                          float acc[2][4][4]){
  unsigned a[2][2][4], b[2][4][2];
  load_frag<BS>(Ab,Bb,wm,wn,l4,lc,0,a[0],b[0]);
  #pragma unroll
  for(int ks=0; ks<4; ks++){
    const int cur = ks&1;
    if(ks<3) load_frag<BS>(Ab,Bb,wm,wn,l4,lc,(ks+1)*8,a[cur^1],b[cur^1]);
    #pragma unroll
    for(int ni=0; ni<4; ni++){
      mma8(acc[0][ni], a[cur][0], b[cur][ni]);
      mma8(acc[1][ni], a[cur][1], b[cur][ni]);
    }
  }
}

// ---------------- k_tmp2: Xh / Y via mma, K-chunk 32 -----------------------
// side 0: Xh[r][h][n] = tf32( (u_feat @ cum_uw)[n][h] * cinv[r][n] )
// side 1: Y [r][m][h] = tf32( (v_feat @ cum_vw)[m][h] * rinv[r][m] )
__global__ __launch_bounds__(128) void k_tmp2(const float* __restrict__ uf,
                                              const float* __restrict__ vf){
  __shared__ __align__(16) unsigned smA[64*A_STR];
  __shared__ __align__(16) unsigned smB[32*BU_STR];
  const int side = blockIdx.z, r = blockIdx.y, n0 = blockIdx.x*64;
  const int tid = threadIdx.x;
  const int wid = tid>>5, lane = tid&31, l4 = lane>>2, lc = lane&3;
  const int wm = wid&1, wn = wid>>1;
  const float* feat = (side ? vf : uf) + (size_t)n0*DD;
  const float* wgt  = (side ? g_vw : g_uw) + r*DD*HH;
  float acc[2][4][4];
  #pragma unroll
  for(int i=0;i<2;i++) for(int j=0;j<4;j++) for(int k=0;k<4;k++) acc[i][j][k]=0.f;

  for(int k0=0; k0<DD; k0+=32){
    #pragma unroll
    for(int i=0;i<4;i++){                      // A 64x32 raw
      const int f = tid + i*128, row = f>>3, c = (f&7)*4;
      *reinterpret_cast<uint4*>(smA + row*A_STR + c) =
        *reinterpret_cast<const uint4*>(feat + (size_t)row*DD + k0 + c);
    }
    #pragma unroll
    for(int i=0;i<4;i++){                      // B 32x64 raw
      const int f = tid + i*128, row = f>>4, c = (f&15)*4;
      *reinterpret_cast<uint4*>(smB + row*BU_STR + c) =
        *reinterpret_cast<const uint4*>(wgt + (size_t)(k0+row)*HH + c);
    }
    __syncthreads();
    chunk_mma<BU_STR>(smA, smB, wm, wn, l4, lc, acc);
    __syncthreads();
  }
  const float* sv = (side ? g_rinv : g_cinv) + r*NN;
  #pragma unroll
  for(int mi=0; mi<2; mi++){
    const int n = n0 + wm*32 + mi*16 + l4;
    const float s0 = sv[n], s1 = sv[n+8];
    #pragma unroll
    for(int ni=0; ni<4; ni++){
      const int h = wn*32 + ni*8 + lc*2;
      if(side==0){
        g_Xh[((size_t)r*HH + h  )*NN + n  ] = __uint_as_float(f2tf(acc[mi][ni][0]*s0));
        g_Xh[((size_t)r*HH + h+1)*NN + n  ] = __uint_as_float(f2tf(acc[mi][ni][1]*s0));
        g_Xh[((size_t)r*HH + h  )*NN + n+8] = __uint_as_float(f2tf(acc[mi][ni][2]*s1));
        g_Xh[((size_t)r*HH + h+1)*NN + n+8] = __uint_as_float(f2tf(acc[mi][ni][3]*s1));
      } else {
        g_Y[((size_t)r*NN + n  )*HH + h  ] = __uint_as_float(f2tf(acc[mi][ni][0]*s0));
        g_Y[((size_t)r*NN + n  )*HH + h+1] = __uint_as_float(f2tf(acc[mi][ni][1]*s0));
        g_Y[((size_t)r*NN + n+8)*HH + h  ] = __uint_as_float(f2tf(acc[mi][ni][2]*s1));
        g_Y[((size_t)r*NN + n+8)*HH + h+1] = __uint_as_float(f2tf(acc[mi][ni][3]*s1));
      }
    }
  }
}

// ---------------- dominant kernel: dual GEMM, K32 chunks, 3-stage cp.async -
// z=0:  T_u[r][pos][h] = sum_m supp[r][ulist[pos]][m] * Y[r][m][h]  (compact rows)
// z=1:  Tvt[r][h][m]   = sum_n Xh[r][h][n] * supp[r][n][m]          (dense)
__global__ __launch_bounds__(256,2) void k_gemm(const float* __restrict__ supp){
  extern __shared__ __align__(16) unsigned char smbuf[];
  const int r = blockIdx.y;
  const int tid = threadIdx.x;
  const int wid = tid>>5, lane = tid&31, l4 = lane>>2, lc = lane&3;
  const uint32_t smb = (uint32_t)__cvta_generic_to_shared(smbuf);
  float acc[2][4][4];
  #pragma unroll
  for(int i=0;i<2;i++) for(int j=0;j<4;j++) for(int k=0;k<4;k++) acc[i][j][k]=0.f;

  if(blockIdx.z == 0){
    const int cnt = g_ucnt;
    const int n0 = blockIdx.x*128;
    if(n0 >= cnt) return;
    const int wm = wid & 3, wn = wid >> 2;          // 4x2 warp grid
    const float* Bp = g_Y + (size_t)r*NN*HH;
    const float* aptr[4];
    #pragma unroll
    for(int i=0;i<4;i++){
      const int rowi = (tid + i*256)>>3;            // 0..127
      int nn = n0 + rowi; if(nn >= cnt) nn = cnt-1;
      aptr[i] = supp + (size_t)r*NN*NN + (size_t)g_ulist[nn]*NN;
    }
    auto load = [&](int j){
      const uint32_t sa = smb + (uint32_t)(j%3)*STG_BYTES;
      const uint32_t sb = sa + 128*A_STR*4;
      const int k0 = j*32;
      #pragma unroll
      for(int i=0;i<4;i++){                         // A 128x32 gathered rows
        const int f = tid + i*256, row = f>>3, c = (f&7)*4;
        cpa16(sa + (uint32_t)(row*A_STR + c)*4u, aptr[i] + k0 + c);
      }
      #pragma unroll
      for(int i=0;i<2;i++){                         // B 32x64
        const int f = tid + i*256, row = f>>4, c = (f&15)*4;
        cpa16(sb + (uint32_t)(row*BU_STR + c)*4u, Bp + (size_t)(k0+row)*HH + c);
      }
    };
    load(0); CP_COMMIT; load(1); CP_COMMIT;
    for(int it=0; it<NN/32; it++){
      CP_WAIT1; __syncthreads();
      const unsigned* Ab = (const unsigned*)(smbuf + (it%3)*STG_BYTES);
      chunk_mma<BU_STR>(Ab, Ab + 128*A_STR, wm, wn, l4, lc, acc);
      if(it+2 < NN/32) load(it+2);
      CP_COMMIT;
    }
    float* Out = g_Tu + ((size_t)r*NN + n0)*HH;
    #pragma unroll
    for(int mi=0; mi<2; mi++){
      const int r0 = wm*32 + mi*16 + l4;
      #pragma unroll
      for(int ni=0; ni<4; ni++){
        const int h = wn*32 + ni*8 + lc*2;
        if(n0+r0 < cnt)
          *reinterpret_cast<float2*>(&Out[(size_t)r0*HH + h])     = make_float2(acc[mi][ni][0], acc[mi][ni][1]);
        if(n0+r0+8 < cnt)
          *reinterpret_cast<float2*>(&Out[(size_t)(r0+8)*HH + h]) = make_float2(acc[mi][ni][2], acc[mi][ni][3]);
      }
    }
  } else {
    const int m0 = blockIdx.x*128;
    const int wm = wid & 1, wn = wid >> 1;          // 2x4 warp grid
    const float* A  = g_Xh + (size_t)r*HH*NN;       // [h][n]
    const float* Bp = supp + (size_t)r*NN*NN + m0;  // rows n(K), cols m
    auto load = [&](int j){
      const uint32_t sa = smb + (uint32_t)(j%3)*STG_BYTES;
      const uint32_t sb = sa + 64*A_STR*4;
      const int k0 = j*32;
      #pragma unroll
      for(int i=0;i<2;i++){                         // A 64x32
        const int f = tid + i*256, row = f>>3, c = (f&7)*4;
        cpa16(sa + (uint32_t)(row*A_STR + c)*4u, A + (size_t)row*NN + k0 + c);
      }
      #pragma unroll
      for(int i=0;i<4;i++){                         // B 32x128
        const int f = tid + i*256, row = f>>5, c = (f&31)*4;
        cpa16(sb + (uint32_t)(row*BV_STR + c)*4u, Bp + (size_t)(k0+row)*NN + c);
      }
    };
    load(0); CP_COMMIT; load(1); CP_COMMIT;
    for(int it=0; it<NN/32; it++){
      CP_WAIT1; __syncthreads();
      const unsigned* Ab = (const unsigned*)(smbuf + (it%3)*STG_BYTES);
      chunk_mma<BV_STR>(Ab, Ab + 64*A_STR, wm, wn, l4, lc, acc);
      if(it+2 < NN/32) load(it+2);
      CP_COMMIT;
    }
    float* Out = g_Tvt + (size_t)r*HH*NN + m0;
    #pragma unroll
    for(int mi=0; mi<2; mi++){
      const int hr = wm*32 + mi*16 + l4;
      #pragma unroll
      for(int ni=0; ni<4; ni++){
        const int mcol = wn*32 + ni*8 + lc*2;
        *reinterpret_cast<float2*>(&Out[(size_t)hr*NN + mcol])     = make_float2(acc[mi][ni][0], acc[mi][ni][1]);
        *reinterpret_cast<float2*>(&Out[(size_t)(hr+8)*NN + mcol]) = make_float2(acc[mi][ni][2], acc[mi][ni][3]);
      }
    }
  }
}

// ---------------- gather + bias + relu -------------------------------------
__global__ void k_out(const int* __restrict__ u, const int* __restrict__ v,
                      const float* __restrict__ bias, float* __restrict__ out){
  const int b = blockIdx.x;
  const int h = threadIdx.x;  // 64
  const int ub = u[b], vb = v[b];
  const int up = g_upos[ub];
  float su = bias[h], sv = bias[h];
  #pragma unroll
  for(int r=0;r<RR;r++){
    su += g_cinv[r*NN + ub] * g_Tu [((size_t)r*NN + up)*HH + h];
    sv += g_rinv[r*NN + vb] * g_Tvt[((size_t)r*HH + h)*NN + vb];
  }
  out[(size_t)b*HH + h]        = fmaxf(su, 0.f);
  out[(size_t)(BB + b)*HH + h] = fmaxf(sv, 0.f);
}

// ---------------- launch ----------------------------------------------------
extern "C" void kernel_launch(void* const* d_in, const int* in_sizes, int n_in,
                              void* d_out, int out_size){
  (void)in_sizes; (void)n_in; (void)out_size;
  const float* u_feat = (const float*)d_in[0];
  const float* v_feat = (const float*)d_in[1];
  const int*   u      = (const int*)  d_in[2];
  const int*   v      = (const int*)  d_in[3];
  const float* supp   = (const float*)d_in[4];
  const float* u_w    = (const float*)d_in[5];
  const float* v_w    = (const float*)d_in[6];
  const float* u_bias = (const float*)d_in[7];
  float* out = (float*)d_out;

  static int attr_done = 0;
  if(!attr_done){
    cudaFuncSetAttribute(k_gemm, cudaFuncAttributeMaxDynamicSharedMemorySize, DYN_BYTES);
    attr_done = 1;
  }

  k_zero   <<<16, 256>>>();
  k_flag   <<<16, 256>>>(u);
  k_scan   <<<1, 1024>>>();
  k_sums   <<<dim3(32, 8, RR), 128>>>(supp);
  k_reduce <<<160, 256>>>();
  k_weights<<<64, 256>>>(u_w, v_w);
  k_tmp2   <<<dim3(64, RR, 2), 128>>>(u_feat, v_feat);
  k_gemm   <<<dim3(32, RR, 2), 256, DYN_BYTES>>>(supp);
  k_out    <<<BB, HH>>>(u, v, u_bias, out);
}